// round 9
// baseline (speedup 1.0000x reference)
#include <cuda_runtime.h>
#include <math.h>

#define Bb 8
#define Tt 2048
#define Dd 768
#define VQ 64
#define L2b 12
#define HID 1024
#define KK 4096
#define BT (Bb*Tt)
#define EPS_N 1e-6f
#define EPS_BN 1e-5f

__device__ float g_z0[KK*HID];
__device__ float g_z1[KK*HID];
__device__ float g_scale[HID];
__device__ float g_shift[HID];
__device__ float g_embed[KK*VQ];
__device__ float g_ck[KK];
__device__ float g_hn[BT*VQ];
__device__ int   g_code[BT];
__device__ float g_psum[4*32*HID];
__device__ float g_psq[4*32*HID];

// packed fp32x2 FMA (bitwise-identical to 2x scalar fp32 fma)
__device__ __forceinline__ float2 f2fma(float2 a, float2 b, float2 c) {
    float2 d;
    asm("fma.rn.f32x2 %0, %1, %2, %3;"
        : "=l"(reinterpret_cast<unsigned long long&>(d))
        : "l"(reinterpret_cast<unsigned long long&>(a)),
          "l"(reinterpret_cast<unsigned long long&>(b)),
          "l"(reinterpret_cast<unsigned long long&>(c)));
    return d;
}
__device__ __forceinline__ float2 f2dup(float x) { return make_float2(x, x); }

// ---------------- layer 0 ----------------
__global__ void k_layer0(const float* __restrict__ w_in, const float* __restrict__ b_in) {
    int idx = blockIdx.x * blockDim.x + threadIdx.x;
    int k = idx >> 10, h = idx & 1023;
    const float* w = w_in + h * L2b;
    float s = b_in[h];
#pragma unroll
    for (int j = 0; j < L2b; j++)
        if ((k >> (11 - j)) & 1) s += w[j];
    g_z0[idx] = s;
}

// ---------------- BN0 closed form ----------------
__global__ void k_bn0(const float* __restrict__ w_in, const float* __restrict__ b_in,
                      const float* __restrict__ gamma, const float* __restrict__ beta) {
    int h = blockIdx.x * blockDim.x + threadIdx.x;
    if (h >= HID) return;
    float s = 0.f, q = 0.f;
#pragma unroll
    for (int j = 0; j < L2b; j++) { float w = w_in[h * L2b + j]; s += w; q += w * w; }
    float m = b_in[h] + 0.5f * s;
    float rstd = (float)(1.0 / sqrt(0.25 * (double)q + (double)EPS_BN));
    float sc = gamma[h] * rstd;
    g_scale[h] = sc;
    g_shift[h] = beta[h] - m * sc;
}

// ---------------- BN finalize from GEMM partials ----------------
__global__ void k_bnfin(int layer, const float* __restrict__ gamma, const float* __restrict__ beta) {
    int h = blockIdx.x * blockDim.x + threadIdx.x;   // 8 x 128 = 1024
    double s0 = 0, s1 = 0, s2 = 0, s3 = 0, q0 = 0, q1 = 0, q2 = 0, q3 = 0;
    const float* ps = g_psum + layer * 32 * HID + h;
    const float* pq = g_psq + layer * 32 * HID + h;
#pragma unroll
    for (int p = 0; p < 32; p += 4) {
        s0 += (double)ps[(p + 0) * HID]; q0 += (double)pq[(p + 0) * HID];
        s1 += (double)ps[(p + 1) * HID]; q1 += (double)pq[(p + 1) * HID];
        s2 += (double)ps[(p + 2) * HID]; q2 += (double)pq[(p + 2) * HID];
        s3 += (double)ps[(p + 3) * HID]; q3 += (double)pq[(p + 3) * HID];
    }
    double m = ((s0 + s1) + (s2 + s3)) / 4096.0;
    double var = ((q0 + q1) + (q2 + q3)) / 4096.0 - m * m;
    if (var < 0.0) var = 0.0;
    float rstd = (float)(1.0 / sqrt(var + (double)EPS_BN));
    float sc = gamma[h] * rstd;
    g_scale[h] = sc;
    g_shift[h] = beta[h] - (float)m * sc;
}

#define BN8(BUF) \
    As[BUF][lk+0][lr]=fmaxf(0.f,fmaf(a0.x,s0.x,h0.x)); \
    As[BUF][lk+1][lr]=fmaxf(0.f,fmaf(a0.y,s0.y,h0.y)); \
    As[BUF][lk+2][lr]=fmaxf(0.f,fmaf(a0.z,s0.z,h0.z)); \
    As[BUF][lk+3][lr]=fmaxf(0.f,fmaf(a0.w,s0.w,h0.w)); \
    As[BUF][lk+4][lr]=fmaxf(0.f,fmaf(a1.x,s1.x,h1.x)); \
    As[BUF][lk+5][lr]=fmaxf(0.f,fmaf(a1.y,s1.y,h1.y)); \
    As[BUF][lk+6][lr]=fmaxf(0.f,fmaf(a1.z,s1.z,h1.z)); \
    As[BUF][lk+7][lr]=fmaxf(0.f,fmaf(a1.w,s1.w,h1.w)); \
    Bs[BUF][lk+0][lr]=b0.x; Bs[BUF][lk+1][lr]=b0.y; \
    Bs[BUF][lk+2][lr]=b0.z; Bs[BUF][lk+3][lr]=b0.w; \
    Bs[BUF][lk+4][lr]=b1.x; Bs[BUF][lk+5][lr]=b1.y; \
    Bs[BUF][lk+6][lr]=b1.z; Bs[BUF][lk+7][lr]=b1.w;

// ---------------- mid GEMM (f32x2): C = relu(bn(A)) @ W^T + bias ----------------
__global__ __launch_bounds__(256, 2) void k_gemm(int src, int layer,
                                                 const float* __restrict__ W,
                                                 const float* __restrict__ bias) {
    const float* __restrict__ A = src ? g_z1 : g_z0;
    float* __restrict__ C       = src ? g_z0 : g_z1;
    __shared__ float As[2][16][128];
    __shared__ float Bs[2][16][128];
    const int tid = threadIdx.x;
    const int brow = blockIdx.y * 128, bcol = blockIdx.x * 128;
    const int lr = tid >> 1, lk = (tid & 1) * 8;
    const int tx = tid & 15, ty = tid >> 4;
    const float* Ap = A + (size_t)(brow + lr) * HID + lk;
    const float* Wp = W + (size_t)(bcol + lr) * HID + lk;
    float4 a0, a1, b0, b1;
    a0 = *(const float4*)Ap;  a1 = *(const float4*)(Ap + 4);
    b0 = *(const float4*)Wp;  b1 = *(const float4*)(Wp + 4);
    {
        float4 s0 = *(const float4*)&g_scale[lk], s1 = *(const float4*)&g_scale[lk + 4];
        float4 h0 = *(const float4*)&g_shift[lk], h1 = *(const float4*)&g_shift[lk + 4];
        BN8(0)
    }
    __syncthreads();
    float2 acc2[4][8];
#pragma unroll
    for (int i = 0; i < 4; i++)
#pragma unroll
        for (int j = 0; j < 8; j++) acc2[i][j] = make_float2(0.f, 0.f);

    for (int t = 0; t < 64; t++) {
        int cur = t & 1, nx = cur ^ 1;
        if (t < 63) {
            int kn = (t + 1) * 16;
            a0 = *(const float4*)(Ap + kn); a1 = *(const float4*)(Ap + kn + 4);
            b0 = *(const float4*)(Wp + kn); b1 = *(const float4*)(Wp + kn + 4);
        }
#pragma unroll
        for (int kk = 0; kk < 16; kk++) {
            float2 ap[4];
            *(float4*)&ap[0] = *(const float4*)&As[cur][kk][ty * 4];
            *(float4*)&ap[2] = *(const float4*)&As[cur][kk][64 + ty * 4];
            float br[8];
            *(float4*)&br[0] = *(const float4*)&Bs[cur][kk][tx * 4];
            *(float4*)&br[4] = *(const float4*)&Bs[cur][kk][64 + tx * 4];
#pragma unroll
            for (int j = 0; j < 8; j++) {
                float2 bd = f2dup(br[j]);
#pragma unroll
                for (int ip = 0; ip < 4; ip++)
                    acc2[ip][j] = f2fma(ap[ip], bd, acc2[ip][j]);
            }
        }
        if (t < 63) {
            int kn = (t + 1) * 16 + lk;
            float4 s0 = *(const float4*)&g_scale[kn], s1 = *(const float4*)&g_scale[kn + 4];
            float4 h0 = *(const float4*)&g_shift[kn], h1 = *(const float4*)&g_shift[kn + 4];
            if (nx) { BN8(1) } else { BN8(0) }
        }
        __syncthreads();
    }
    // epilogue
    float bj[8];
    *(float4*)&bj[0] = *(const float4*)&bias[bcol + tx * 4];
    *(float4*)&bj[4] = *(const float4*)&bias[bcol + 64 + tx * 4];
    float cs[8] = {}, cq[8] = {};
#pragma unroll
    for (int ip = 0; ip < 4; ip++) {
#pragma unroll
        for (int c = 0; c < 2; c++) {
            int row = brow + ((ip >> 1) ? 64 : 0) + ty * 4 + (ip & 1) * 2 + c;
            float v[8];
#pragma unroll
            for (int j = 0; j < 8; j++) {
                float val = (c ? acc2[ip][j].y : acc2[ip][j].x) + bj[j];
                v[j] = val;
                cs[j] += val;
                cq[j] += val * val;
            }
            *(float4*)&C[(size_t)row * HID + bcol + tx * 4]      = *(float4*)&v[0];
            *(float4*)&C[(size_t)row * HID + bcol + 64 + tx * 4] = *(float4*)&v[4];
        }
    }
    float* reds = &As[0][0][0];
    float* redq = reds + 2048;
#pragma unroll
    for (int j = 0; j < 8; j++) {
        int c = (j < 4) ? (tx * 4 + j) : (64 + tx * 4 + j - 4);
        reds[ty * 128 + c] = cs[j];
        redq[ty * 128 + c] = cq[j];
    }
    __syncthreads();
    if (tid < 128) {
        float s = 0.f, q = 0.f;
#pragma unroll
        for (int yy = 0; yy < 16; yy++) { s += reds[yy * 128 + tid]; q += redq[yy * 128 + tid]; }
        g_psum[(layer * 32 + blockIdx.y) * HID + bcol + tid] = s;
        g_psq [(layer * 32 + blockIdx.y) * HID + bcol + tid] = q;
    }
}

// ---------------- embed v2: 64x64 tile GEMM + fused L2 norm ----------------
__global__ __launch_bounds__(256) void k_embed(const float* __restrict__ Wout,
                                               const float* __restrict__ bout) {
    __shared__ float As[16][68];
    __shared__ float Ws[16][68];
    __shared__ float red[64][9];
    __shared__ float fac[64];
    const int tid = threadIdx.x;
    const int r0 = blockIdx.x * 64;
    const int tx = tid & 7, ty2 = tid >> 3;     // ty2: 0..31, 2 rows each
    const int lrow = tid >> 2, lkc = (tid & 3) * 4;

    float2 acc2[8];
#pragma unroll
    for (int j = 0; j < 8; j++) acc2[j] = make_float2(0.f, 0.f);

    for (int k0 = 0; k0 < HID; k0 += 16) {
        {
            float4 a = *(const float4*)&g_z0[(size_t)(r0 + lrow) * HID + k0 + lkc];
            float4 sc = *(const float4*)&g_scale[k0 + lkc];
            float4 sh = *(const float4*)&g_shift[k0 + lkc];
            As[lkc + 0][lrow] = fmaxf(0.f, fmaf(a.x, sc.x, sh.x));
            As[lkc + 1][lrow] = fmaxf(0.f, fmaf(a.y, sc.y, sh.y));
            As[lkc + 2][lrow] = fmaxf(0.f, fmaf(a.z, sc.z, sh.z));
            As[lkc + 3][lrow] = fmaxf(0.f, fmaf(a.w, sc.w, sh.w));
            float4 w = *(const float4*)&Wout[(size_t)lrow * HID + k0 + lkc];
            Ws[lkc + 0][lrow] = w.x; Ws[lkc + 1][lrow] = w.y;
            Ws[lkc + 2][lrow] = w.z; Ws[lkc + 3][lrow] = w.w;
        }
        __syncthreads();
#pragma unroll
        for (int kk = 0; kk < 16; kk++) {
            float2 ap = *(const float2*)&As[kk][ty2 * 2];
            float br[8];
            *(float4*)&br[0] = *(const float4*)&Ws[kk][tx * 8];
            *(float4*)&br[4] = *(const float4*)&Ws[kk][tx * 8 + 4];
#pragma unroll
            for (int j = 0; j < 8; j++)
                acc2[j] = f2fma(ap, f2dup(br[j]), acc2[j]);
        }
        __syncthreads();
    }
    float bj[8];
    *(float4*)&bj[0] = *(const float4*)&bout[tx * 8];
    *(float4*)&bj[4] = *(const float4*)&bout[tx * 8 + 4];
    float y[2][8];
#pragma unroll
    for (int c = 0; c < 2; c++) {
        float p = 0.f;
#pragma unroll
        for (int j = 0; j < 8; j++) {
            y[c][j] = (c ? acc2[j].y : acc2[j].x) + bj[j];
            p = fmaf(y[c][j], y[c][j], p);
        }
        red[ty2 * 2 + c][tx] = p;
    }
    __syncthreads();
    if (tid < 64) {
        float tot = 0.f;
#pragma unroll
        for (int q = 0; q < 8; q++) tot += red[tid][q];
        float f = 1.f / (sqrtf(tot) + EPS_N);
        fac[tid] = f;
        g_ck[r0 + tid] = 0.5f * tot * f * f;
    }
    __syncthreads();
#pragma unroll
    for (int c = 0; c < 2; c++) {
        float f = fac[ty2 * 2 + c];
        float v[8];
#pragma unroll
        for (int j = 0; j < 8; j++) v[j] = y[c][j] * f;
        float* op = &g_embed[(size_t)(r0 + ty2 * 2 + c) * VQ + tx * 8];
        *(float4*)op       = *(float4*)&v[0];
        *(float4*)(op + 4) = *(float4*)&v[4];
    }
}

// ---------------- projection + fused row L2 norm (f32x2) ----------------
__global__ __launch_bounds__(256) void k_proj(const float* __restrict__ h_in,
                                              const float* __restrict__ proj_w,
                                              const float* __restrict__ proj_b) {
    __shared__ float Hs[16][64];
    __shared__ float Ws[16][64];
    __shared__ float red[64][17];
    __shared__ float fac[64];
    int tid = threadIdx.x;
    int b = blockIdx.y;
    int t0 = blockIdx.x * 64;
    int tx = tid & 15, ty = tid >> 4;
    float2 acc2[2][4];
#pragma unroll
    for (int i = 0; i < 2; i++)
#pragma unroll
        for (int j = 0; j < 4; j++) acc2[i][j] = make_float2(0.f, 0.f);
    const float* hb = h_in + (size_t)b * Dd * Tt;
    for (int d0 = 0; d0 < Dd; d0 += 16) {
        {
            int j0 = tid * 4;
            int dd = j0 >> 6, tt = j0 & 63;
            *(float4*)&Hs[dd][tt] = *(const float4*)&hb[(size_t)(d0 + dd) * Tt + t0 + tt];
        }
        {
            int v = tid >> 2, dq = (tid & 3) * 4;
            float4 x = *(const float4*)&proj_w[(size_t)v * Dd + d0 + dq];
            Ws[dq + 0][v] = x.x; Ws[dq + 1][v] = x.y; Ws[dq + 2][v] = x.z; Ws[dq + 3][v] = x.w;
        }
        __syncthreads();
#pragma unroll
        for (int dd = 0; dd < 16; dd++) {
            float2 ap[2];
            *(float4*)&ap[0] = *(const float4*)&Hs[dd][ty * 4];
            float br[4];
            *(float4*)&br[0] = *(const float4*)&Ws[dd][tx * 4];
#pragma unroll
            for (int j = 0; j < 4; j++) {
                float2 bd = f2dup(br[j]);
#pragma unroll
                for (int ip = 0; ip < 2; ip++)
                    acc2[ip][j] = f2fma(ap[ip], bd, acc2[ip][j]);
            }
        }
        __syncthreads();
    }
    float bj[4];
    *(float4*)&bj[0] = *(const float4*)&proj_b[tx * 4];
#pragma unroll
    for (int ip = 0; ip < 2; ip++) {
#pragma unroll
        for (int c = 0; c < 2; c++) {
            int r = ty * 4 + ip * 2 + c;
            float p = 0.f;
#pragma unroll
            for (int j = 0; j < 4; j++) {
                float val = (c ? acc2[ip][j].y : acc2[ip][j].x) + bj[j];
                p = fmaf(val, val, p);
            }
            red[r][tx] = p;
        }
    }
    __syncthreads();
    if (tid < 64) {
        float tot = 0.f;
#pragma unroll
        for (int q = 0; q < 16; q++) tot += red[tid][q];
        fac[tid] = 1.f / (sqrtf(tot) + EPS_N);
    }
    __syncthreads();
#pragma unroll
    for (int ip = 0; ip < 2; ip++) {
#pragma unroll
        for (int c = 0; c < 2; c++) {
            int r = ty * 4 + ip * 2 + c;
            float f = fac[r];
            float v[4];
#pragma unroll
            for (int j = 0; j < 4; j++)
                v[j] = ((c ? acc2[ip][j].y : acc2[ip][j].x) + bj[j]) * f;
            size_t row = (size_t)b * Tt + t0 + r;
            *(float4*)&g_hn[row * VQ + tx * 4] = *(float4*)&v[0];
        }
    }
}

// ---------------- argmax (f32x2): 64 rows x 128 codes/tile ----------------
__global__ __launch_bounds__(128, 4) void k_argmax() {
    __shared__ float hsT[64][64];
    __shared__ float esT[64][128];
    const int tid = threadIdx.x, r0 = blockIdx.x * 64;
    const int tx = tid & 15, ty = tid >> 4;
#pragma unroll
    for (int i = 0; i < 8; i++) {
        int f = tid + i * 128;
        int r = f >> 4, vq = (f & 15) * 4;
        float4 x = *(const float4*)&g_hn[(size_t)(r0 + r) * VQ + vq];
        hsT[vq + 0][r] = x.x; hsT[vq + 1][r] = x.y;
        hsT[vq + 2][r] = x.z; hsT[vq + 3][r] = x.w;
    }
    float best[8]; int bidx[8];
#pragma unroll
    for (int i = 0; i < 8; i++) { best[i] = -3.4e38f; bidx[i] = 0; }

    for (int kt = 0; kt < 32; kt++) {
        int kb = kt * 128;
        __syncthreads();
#pragma unroll
        for (int i = 0; i < 16; i++) {
            int f = tid + i * 128;
            int code = f >> 4, vq = (f & 15) * 4;
            float4 x = *(const float4*)&g_embed[(size_t)(kb + code) * VQ + vq];
            esT[vq + 0][code] = x.x; esT[vq + 1][code] = x.y;
            esT[vq + 2][code] = x.z; esT[vq + 3][code] = x.w;
        }
        __syncthreads();
        float2 acc2[4][8];
#pragma unroll
        for (int i = 0; i < 4; i++)
#pragma unroll
            for (int j = 0; j < 8; j++) acc2[i][j] = make_float2(0.f, 0.f);
#pragma unroll 4
        for (int v = 0; v < 64; v++) {
            float2 ap[4];
            *(float4*)&ap[0] = *(const float4*)&hsT[v][ty * 4];
            *(float4*)&ap[2] = *(const float4*)&hsT[v][32 + ty * 4];
            float br[8];
            *(float4*)&br[0] = *(const float4*)&esT[v][tx * 4];
            *(float4*)&br[4] = *(const float4*)&esT[v][64 + tx * 4];
#pragma unroll
            for (int j = 0; j < 8; j++) {
                float2 bd = f2dup(br[j]);
#pragma unroll
                for (int ip = 0; ip < 4; ip++)
                    acc2[ip][j] = f2fma(ap[ip], bd, acc2[ip][j]);
            }
        }
#pragma unroll
        for (int j = 0; j < 8; j++) {
            int kg = kb + ((j < 4) ? (tx * 4 + j) : (64 + tx * 4 + j - 4));
            float ck = g_ck[kg];
#pragma unroll
            for (int ip = 0; ip < 4; ip++) {
                float sx = acc2[ip][j].x - ck;
                float sy = acc2[ip][j].y - ck;
                if (sx > best[ip * 2 + 0]) { best[ip * 2 + 0] = sx; bidx[ip * 2 + 0] = kg; }
                if (sy > best[ip * 2 + 1]) { best[ip * 2 + 1] = sy; bidx[ip * 2 + 1] = kg; }
            }
        }
    }
    __syncthreads();
    float* rb = &esT[0][0];
    int* ri = (int*)(rb + 1024);
#pragma unroll
    for (int ip = 0; ip < 4; ip++) {
#pragma unroll
        for (int c = 0; c < 2; c++) {
            int r = ((ip >> 1) ? 32 : 0) + ty * 4 + (ip & 1) * 2 + c;
            rb[r * 16 + tx] = best[ip * 2 + c];
            ri[r * 16 + tx] = bidx[ip * 2 + c];
        }
    }
    __syncthreads();
    if (tid < 64) {
        float b = rb[tid * 16]; int ix = ri[tid * 16];
#pragma unroll
        for (int q = 1; q < 16; q++) {
            float s = rb[tid * 16 + q];
            int k2 = ri[tid * 16 + q];
            if (s > b || (s == b && k2 < ix)) { b = s; ix = k2; }
        }
        g_code[r0 + tid] = ix;
    }
}

// ---------------- output ----------------
__global__ __launch_bounds__(256) void k_output(const int* __restrict__ attn_mask,
                                                const float* __restrict__ inv_w,
                                                const float* __restrict__ inv_b,
                                                float* __restrict__ out,
                                                int write_code, float* __restrict__ code_out) {
    __shared__ float es[32][65];
    __shared__ float ws[64][64];
    __shared__ int codes[32];
    __shared__ int msk[32];
    int tid = threadIdx.x;
    int r0 = blockIdx.x * 32;
    if (tid < 32) {
        int i = r0 + tid;
        int c = g_code[i];
        int m = attn_mask[i];
        codes[tid] = c;
        msk[tid] = m;
        if (write_code) code_out[i] = (float)((m == 1) ? c : 0);
    }
    __syncthreads();
    for (int j = tid; j < 32 * 64; j += 256) {
        int r = j >> 6, v = j & 63;
        es[r][v] = (msk[r] == 1) ? g_embed[(size_t)codes[r] * VQ + v] : 0.f;
    }
    int r = tid & 31;
    int ddb = (tid >> 5) * 8;
    for (int d0 = 0; d0 < Dd; d0 += 64) {
        __syncthreads();
        for (int j = tid; j < 64 * 64; j += 256) {
            int dd = j >> 6, v = j & 63;
            ws[dd][v] = inv_w[(size_t)(d0 + dd) * VQ + v];
        }
        __syncthreads();
#pragma unroll
        for (int q = 0; q < 8; q++) {
            int dd = ddb + q;
            float s = inv_b[d0 + dd];
#pragma unroll
            for (int v = 0; v < 64; v += 4) {
                float4 w4 = *(float4*)&ws[dd][v];
                s = fmaf(es[r][v + 0], w4.x, s);
                s = fmaf(es[r][v + 1], w4.y, s);
                s = fmaf(es[r][v + 2], w4.z, s);
                s = fmaf(es[r][v + 3], w4.w, s);
            }
            out[(size_t)(r0 + r) * Dd + d0 + dd] = s;
        }
    }
}

// ---------------- host launcher ----------------
extern "C" void kernel_launch(void* const* d_in, const int* in_sizes, int n_in,
                              void* d_out, int out_size) {
    const float* h_in      = (const float*)d_in[0];
    const int*   attn_mask = (const int*)  d_in[1];
    const float* proj_w    = (const float*)d_in[2];
    const float* proj_b    = (const float*)d_in[3];
    const float* inv_w     = (const float*)d_in[4];
    const float* inv_b     = (const float*)d_in[5];
    const float* mlp_w_in  = (const float*)d_in[6];
    const float* mlp_b_in  = (const float*)d_in[7];
    const float* mlp_w_mid = (const float*)d_in[8];
    const float* mlp_b_mid = (const float*)d_in[9];
    const float* mlp_w_out = (const float*)d_in[10];
    const float* mlp_b_out = (const float*)d_in[11];
    const float* bn_gamma  = (const float*)d_in[12];
    const float* bn_beta   = (const float*)d_in[13];
    float* out = (float*)d_out;

    k_layer0<<<KK * HID / 256, 256>>>(mlp_w_in, mlp_b_in);
    k_bn0<<<HID / 256, 256>>>(mlp_w_in, mlp_b_in, bn_gamma, bn_beta);

    dim3 gg(HID / 128, KK / 128);
    for (int L = 0; L < 4; L++) {
        k_gemm<<<gg, 256>>>(L & 1, L, mlp_w_mid + (size_t)L * HID * HID, mlp_b_mid + L * HID);
        k_bnfin<<<8, 128>>>(L, bn_gamma + (L + 1) * HID, bn_beta + (L + 1) * HID);
    }

    k_embed<<<KK / 64, 256>>>(mlp_w_out, mlp_b_out);

    dim3 pg(Tt / 64, Bb);
    k_proj<<<pg, 256>>>(h_in, proj_w, proj_b);

    k_argmax<<<BT / 64, 128>>>();

    const long long qelems = (long long)BT * Dd;
    int write_code = (out_size >= qelems + BT) ? 1 : 0;
    k_output<<<BT / 32, 256>>>(attn_mask, inv_w, inv_b, out, write_code, out + qelems);
}

// round 12
// speedup vs baseline: 1.3534x; 1.3534x over previous
#include <cuda_runtime.h>
#include <math.h>

#define Bb 8
#define Tt 2048
#define Dd 768
#define VQ 64
#define L2b 12
#define HID 1024
#define KK 4096
#define BT (Bb*Tt)
#define EPS_N 1e-6f
#define EPS_BN 1e-5f

__device__ float g_z0[KK*HID];
__device__ float g_z1[KK*HID];
__device__ float g_scale[HID];
__device__ float g_shift[HID];
__device__ float g_embed[KK*VQ];
__device__ float g_ck[KK];
__device__ float g_hn[BT*VQ];
__device__ int   g_code[BT];
__device__ float g_psum[4*32*HID];
__device__ float g_psq[4*32*HID];

// ---------------- layer 0 ----------------
__global__ void k_layer0(const float* __restrict__ w_in, const float* __restrict__ b_in) {
    int idx = blockIdx.x * blockDim.x + threadIdx.x;
    int k = idx >> 10, h = idx & 1023;
    const float* w = w_in + h * L2b;
    float s = b_in[h];
#pragma unroll
    for (int j = 0; j < L2b; j++)
        if ((k >> (11 - j)) & 1) s += w[j];
    g_z0[idx] = s;
}

// ---------------- BN0 closed form (exact over full enumeration) ----------------
__global__ void k_bn0(const float* __restrict__ w_in, const float* __restrict__ b_in,
                      const float* __restrict__ gamma, const float* __restrict__ beta) {
    int h = blockIdx.x * blockDim.x + threadIdx.x;
    if (h >= HID) return;
    float s = 0.f, q = 0.f;
#pragma unroll
    for (int j = 0; j < L2b; j++) { float w = w_in[h * L2b + j]; s += w; q += w * w; }
    float m = b_in[h] + 0.5f * s;
    float rstd = (float)(1.0 / sqrt(0.25 * (double)q + (double)EPS_BN));
    float sc = gamma[h] * rstd;
    g_scale[h] = sc;
    g_shift[h] = beta[h] - m * sc;
}

// fused BN-finalize prologue: fill s_scale/s_shift[HID] from partials (or g_scale if sl<0)
__device__ __forceinline__ void bn_prologue(int sl, const float* __restrict__ gamma,
                                            const float* __restrict__ beta,
                                            float* s_scale, float* s_shift,
                                            int tid, int NT) {
    if (sl < 0) {
        for (int h = tid; h < HID; h += NT) {
            s_scale[h] = g_scale[h];
            s_shift[h] = g_shift[h];
        }
    } else {
        const float* ps = g_psum + sl * 32 * HID;
        const float* pq = g_psq + sl * 32 * HID;
        for (int h = tid; h < HID; h += NT) {
            double s = 0.0, q = 0.0;
#pragma unroll 8
            for (int p = 0; p < 32; p++) {
                s += (double)ps[p * HID + h];
                q += (double)pq[p * HID + h];
            }
            double m = s / 4096.0;
            double var = q / 4096.0 - m * m;
            if (var < 0.0) var = 0.0;
            float rstd = (float)(1.0 / sqrt(var + (double)EPS_BN));
            float sc = gamma[h] * rstd;
            s_scale[h] = sc;
            s_shift[h] = beta[h] - (float)m * sc;
        }
    }
}

#define BN8(BUF) \
    As[BUF][lk+0][lr]=fmaxf(0.f,fmaf(a0.x,s0.x,h0.x)); \
    As[BUF][lk+1][lr]=fmaxf(0.f,fmaf(a0.y,s0.y,h0.y)); \
    As[BUF][lk+2][lr]=fmaxf(0.f,fmaf(a0.z,s0.z,h0.z)); \
    As[BUF][lk+3][lr]=fmaxf(0.f,fmaf(a0.w,s0.w,h0.w)); \
    As[BUF][lk+4][lr]=fmaxf(0.f,fmaf(a1.x,s1.x,h1.x)); \
    As[BUF][lk+5][lr]=fmaxf(0.f,fmaf(a1.y,s1.y,h1.y)); \
    As[BUF][lk+6][lr]=fmaxf(0.f,fmaf(a1.z,s1.z,h1.z)); \
    As[BUF][lk+7][lr]=fmaxf(0.f,fmaf(a1.w,s1.w,h1.w)); \
    Bs[BUF][lk+0][lr]=b0.x; Bs[BUF][lk+1][lr]=b0.y; \
    Bs[BUF][lk+2][lr]=b0.z; Bs[BUF][lk+3][lr]=b0.w; \
    Bs[BUF][lk+4][lr]=b1.x; Bs[BUF][lk+5][lr]=b1.y; \
    Bs[BUF][lk+6][lr]=b1.z; Bs[BUF][lk+7][lr]=b1.w;

// ---------------- mid GEMM: C = relu(bn(A)) @ W^T + bias, fused BN-finalize + BN-stat partials ----------------
__global__ __launch_bounds__(256, 2) void k_gemm(int src, int layer, int stats_layer,
                                                 const float* __restrict__ W,
                                                 const float* __restrict__ bias,
                                                 const float* __restrict__ gamma,
                                                 const float* __restrict__ beta) {
    const float* __restrict__ A = src ? g_z1 : g_z0;
    float* __restrict__ C       = src ? g_z0 : g_z1;
    __shared__ float As[2][16][128];
    __shared__ float Bs[2][16][128];
    __shared__ float s_scale[HID];
    __shared__ float s_shift[HID];
    const int tid = threadIdx.x;
    const int brow = blockIdx.y * 128, bcol = blockIdx.x * 128;
    const int lr = tid >> 1, lk = (tid & 1) * 8;
    const int tx = tid & 15, ty = tid >> 4;

    bn_prologue(stats_layer, gamma, beta, s_scale, s_shift, tid, 256);
    __syncthreads();

    const float* Ap = A + (size_t)(brow + lr) * HID + lk;
    const float* Wp = W + (size_t)(bcol + lr) * HID + lk;
    float4 a0, a1, b0, b1;
    a0 = *(const float4*)Ap;  a1 = *(const float4*)(Ap + 4);
    b0 = *(const float4*)Wp;  b1 = *(const float4*)(Wp + 4);
    {
        float4 s0 = *(const float4*)&s_scale[lk], s1 = *(const float4*)&s_scale[lk + 4];
        float4 h0 = *(const float4*)&s_shift[lk], h1 = *(const float4*)&s_shift[lk + 4];
        BN8(0)
    }
    __syncthreads();
    float acc[8][8] = {};
    for (int t = 0; t < 64; t++) {
        int cur = t & 1, nx = cur ^ 1;
        if (t < 63) {
            int kn = (t + 1) * 16;
            a0 = *(const float4*)(Ap + kn); a1 = *(const float4*)(Ap + kn + 4);
            b0 = *(const float4*)(Wp + kn); b1 = *(const float4*)(Wp + kn + 4);
        }
#pragma unroll
        for (int kk = 0; kk < 16; kk++) {
            float ar[8], br[8];
            *(float4*)&ar[0] = *(const float4*)&As[cur][kk][ty * 4];
            *(float4*)&ar[4] = *(const float4*)&As[cur][kk][64 + ty * 4];
            *(float4*)&br[0] = *(const float4*)&Bs[cur][kk][tx * 4];
            *(float4*)&br[4] = *(const float4*)&Bs[cur][kk][64 + tx * 4];
#pragma unroll
            for (int i = 0; i < 8; i++)
#pragma unroll
                for (int j = 0; j < 8; j++)
                    acc[i][j] = fmaf(ar[i], br[j], acc[i][j]);
        }
        if (t < 63) {
            int kn = (t + 1) * 16 + lk;
            float4 s0 = *(const float4*)&s_scale[kn], s1 = *(const float4*)&s_scale[kn + 4];
            float4 h0 = *(const float4*)&s_shift[kn], h1 = *(const float4*)&s_shift[kn + 4];
            if (nx) { BN8(1) } else { BN8(0) }
        }
        __syncthreads();
    }
    // epilogue: bias + store + column partial stats
    float bj[8];
    *(float4*)&bj[0] = *(const float4*)&bias[bcol + tx * 4];
    *(float4*)&bj[4] = *(const float4*)&bias[bcol + 64 + tx * 4];
    float cs[8] = {}, cq[8] = {};
#pragma unroll
    for (int i = 0; i < 8; i++) {
        int row = brow + ((i < 4) ? (ty * 4 + i) : (64 + ty * 4 + i - 4));
        float v[8];
#pragma unroll
        for (int j = 0; j < 8; j++) {
            v[j] = acc[i][j] + bj[j];
            cs[j] += v[j];
            cq[j] += v[j] * v[j];
        }
        *(float4*)&C[(size_t)row * HID + bcol + tx * 4]      = *(float4*)&v[0];
        *(float4*)&C[(size_t)row * HID + bcol + 64 + tx * 4] = *(float4*)&v[4];
    }
    float* reds = &As[0][0][0];
    float* redq = reds + 2048;
#pragma unroll
    for (int j = 0; j < 8; j++) {
        int c = (j < 4) ? (tx * 4 + j) : (64 + tx * 4 + j - 4);
        reds[ty * 128 + c] = cs[j];
        redq[ty * 128 + c] = cq[j];
    }
    __syncthreads();
    if (tid < 128) {
        float s = 0.f, q = 0.f;
#pragma unroll
        for (int yy = 0; yy < 16; yy++) { s += reds[yy * 128 + tid]; q += redq[yy * 128 + tid]; }
        g_psum[(layer * 32 + blockIdx.y) * HID + bcol + tid] = s;
        g_psq [(layer * 32 + blockIdx.y) * HID + bcol + tid] = q;
    }
}

// ---------------- embed: 64x64 tile GEMM + fused BN-finalize + L2 norm ----------------
__global__ __launch_bounds__(256) void k_embed(const float* __restrict__ Wout,
                                               const float* __restrict__ bout,
                                               const float* __restrict__ gamma,
                                               const float* __restrict__ beta) {
    __shared__ float As[16][68];
    __shared__ float Ws[16][68];
    __shared__ float red[64][9];
    __shared__ float fac[64];
    __shared__ float s_scale[HID];
    __shared__ float s_shift[HID];
    const int tid = threadIdx.x;
    const int r0 = blockIdx.x * 64;
    const int tx = tid & 7, ty2 = tid >> 3;
    const int lrow = tid >> 2, lkc = (tid & 3) * 4;

    bn_prologue(3, gamma, beta, s_scale, s_shift, tid, 256);
    __syncthreads();

    float acc[2][8] = {};
    for (int k0 = 0; k0 < HID; k0 += 16) {
        {
            float4 a = *(const float4*)&g_z0[(size_t)(r0 + lrow) * HID + k0 + lkc];
            float4 sc = *(const float4*)&s_scale[k0 + lkc];
            float4 sh = *(const float4*)&s_shift[k0 + lkc];
            As[lkc + 0][lrow] = fmaxf(0.f, fmaf(a.x, sc.x, sh.x));
            As[lkc + 1][lrow] = fmaxf(0.f, fmaf(a.y, sc.y, sh.y));
            As[lkc + 2][lrow] = fmaxf(0.f, fmaf(a.z, sc.z, sh.z));
            As[lkc + 3][lrow] = fmaxf(0.f, fmaf(a.w, sc.w, sh.w));
            float4 w = *(const float4*)&Wout[(size_t)lrow * HID + k0 + lkc];
            Ws[lkc + 0][lrow] = w.x; Ws[lkc + 1][lrow] = w.y;
            Ws[lkc + 2][lrow] = w.z; Ws[lkc + 3][lrow] = w.w;
        }
        __syncthreads();
#pragma unroll
        for (int kk = 0; kk < 16; kk++) {
            float2 ap = *(const float2*)&As[kk][ty2 * 2];
            float br[8];
            *(float4*)&br[0] = *(const float4*)&Ws[kk][tx * 8];
            *(float4*)&br[4] = *(const float4*)&Ws[kk][tx * 8 + 4];
#pragma unroll
            for (int j = 0; j < 8; j++) {
                acc[0][j] = fmaf(ap.x, br[j], acc[0][j]);
                acc[1][j] = fmaf(ap.y, br[j], acc[1][j]);
            }
        }
        __syncthreads();
    }
    float bj[8];
    *(float4*)&bj[0] = *(const float4*)&bout[tx * 8];
    *(float4*)&bj[4] = *(const float4*)&bout[tx * 8 + 4];
    float y[2][8];
#pragma unroll
    for (int c = 0; c < 2; c++) {
        float p = 0.f;
#pragma unroll
        for (int j = 0; j < 8; j++) {
            y[c][j] = acc[c][j] + bj[j];
            p = fmaf(y[c][j], y[c][j], p);
        }
        red[ty2 * 2 + c][tx] = p;
    }
    __syncthreads();
    if (tid < 64) {
        float tot = 0.f;
#pragma unroll
        for (int q = 0; q < 8; q++) tot += red[tid][q];
        float f = 1.f / (sqrtf(tot) + EPS_N);
        fac[tid] = f;
        g_ck[r0 + tid] = 0.5f * tot * f * f;
    }
    __syncthreads();
#pragma unroll
    for (int c = 0; c < 2; c++) {
        float f = fac[ty2 * 2 + c];
        float v[8];
#pragma unroll
        for (int j = 0; j < 8; j++) v[j] = y[c][j] * f;
        float* op = &g_embed[(size_t)(r0 + ty2 * 2 + c) * VQ + tx * 8];
        *(float4*)op       = *(float4*)&v[0];
        *(float4*)(op + 4) = *(float4*)&v[4];
    }
}

// ---------------- projection + fused row L2 norm ----------------
__global__ __launch_bounds__(256) void k_proj(const float* __restrict__ h_in,
                                              const float* __restrict__ proj_w,
                                              const float* __restrict__ proj_b) {
    __shared__ float Hs[16][64];
    __shared__ float Ws[16][64];
    __shared__ float red[64][16];
    __shared__ float fac[64];
    int tid = threadIdx.x;
    int b = blockIdx.y;
    int t0 = blockIdx.x * 64;
    int tx = tid & 15, ty = tid >> 4;
    float acc[4][4] = {};
    const float* hb = h_in + (size_t)b * Dd * Tt;
    for (int d0 = 0; d0 < Dd; d0 += 16) {
        {
            int j0 = tid * 4;
            int dd = j0 >> 6, tt = j0 & 63;
            *(float4*)&Hs[dd][tt] = *(const float4*)&hb[(size_t)(d0 + dd) * Tt + t0 + tt];
        }
        {
            int v = tid >> 2, dq = (tid & 3) * 4;
            float4 x = *(const float4*)&proj_w[(size_t)v * Dd + d0 + dq];
            Ws[dq + 0][v] = x.x; Ws[dq + 1][v] = x.y; Ws[dq + 2][v] = x.z; Ws[dq + 3][v] = x.w;
        }
        __syncthreads();
#pragma unroll
        for (int dd = 0; dd < 16; dd++) {
            float ar[4], br[4];
            *(float4*)&ar[0] = *(const float4*)&Hs[dd][ty * 4];
            *(float4*)&br[0] = *(const float4*)&Ws[dd][tx * 4];
#pragma unroll
            for (int i = 0; i < 4; i++)
#pragma unroll
                for (int j = 0; j < 4; j++)
                    acc[i][j] = fmaf(ar[i], br[j], acc[i][j]);
        }
        __syncthreads();
    }
    float bj[4];
    *(float4*)&bj[0] = *(const float4*)&proj_b[tx * 4];
#pragma unroll
    for (int i = 0; i < 4; i++) {
        float p = 0.f;
#pragma unroll
        for (int j = 0; j < 4; j++) {
            float v = acc[i][j] + bj[j];
            acc[i][j] = v;
            p = fmaf(v, v, p);
        }
        red[ty * 4 + i][tx] = p;
    }
    __syncthreads();
    if (tid < 64) {
        float tot = 0.f;
#pragma unroll
        for (int q = 0; q < 16; q++) tot += red[tid][q];
        fac[tid] = 1.f / (sqrtf(tot) + EPS_N);
    }
    __syncthreads();
#pragma unroll
    for (int i = 0; i < 4; i++) {
        float f = fac[ty * 4 + i];
        float v[4];
#pragma unroll
        for (int j = 0; j < 4; j++) v[j] = acc[i][j] * f;
        size_t row = (size_t)b * Tt + t0 + ty * 4 + i;
        *(float4*)&g_hn[row * VQ + tx * 4] = *(float4*)&v[0];
    }
}

// ---------------- argmax: 64 rows x 128 codes/tile, 8x8 microtile ----------------
__global__ __launch_bounds__(128, 4) void k_argmax() {
    __shared__ float hsT[64][64];
    __shared__ float esT[64][128];
    const int tid = threadIdx.x, r0 = blockIdx.x * 64;
    const int tx = tid & 15, ty = tid >> 4;
#pragma unroll
    for (int i = 0; i < 8; i++) {
        int f = tid + i * 128;
        int r = f >> 4, vq = (f & 15) * 4;
        float4 x = *(const float4*)&g_hn[(size_t)(r0 + r) * VQ + vq];
        hsT[vq + 0][r] = x.x; hsT[vq + 1][r] = x.y;
        hsT[vq + 2][r] = x.z; hsT[vq + 3][r] = x.w;
    }
    float best[8]; int bidx[8];
#pragma unroll
    for (int i = 0; i < 8; i++) { best[i] = -3.4e38f; bidx[i] = 0; }

    for (int kt = 0; kt < 32; kt++) {
        int kb = kt * 128;
        __syncthreads();
#pragma unroll
        for (int i = 0; i < 16; i++) {
            int f = tid + i * 128;
            int code = f >> 4, vq = (f & 15) * 4;
            float4 x = *(const float4*)&g_embed[(size_t)(kb + code) * VQ + vq];
            esT[vq + 0][code] = x.x; esT[vq + 1][code] = x.y;
            esT[vq + 2][code] = x.z; esT[vq + 3][code] = x.w;
        }
        __syncthreads();
        float acc[8][8] = {};
#pragma unroll 4
        for (int v = 0; v < 64; v++) {
            float ar[8], br[8];
            *(float4*)&ar[0] = *(const float4*)&hsT[v][ty * 4];
            *(float4*)&ar[4] = *(const float4*)&hsT[v][32 + ty * 4];
            *(float4*)&br[0] = *(const float4*)&esT[v][tx * 4];
            *(float4*)&br[4] = *(const float4*)&esT[v][64 + tx * 4];
#pragma unroll
            for (int i = 0; i < 8; i++)
#pragma unroll
                for (int j = 0; j < 8; j++)
                    acc[i][j] = fmaf(ar[i], br[j], acc[i][j]);
        }
#pragma unroll
        for (int j = 0; j < 8; j++) {
            int kg = kb + ((j < 4) ? (tx * 4 + j) : (64 + tx * 4 + j - 4));
            float ck = g_ck[kg];
#pragma unroll
            for (int i = 0; i < 8; i++) {
                float s = acc[i][j] - ck;
                if (s > best[i]) { best[i] = s; bidx[i] = kg; }
            }
        }
    }
    __syncthreads();
    float* rb = &esT[0][0];
    int* ri = (int*)(rb + 1024);
#pragma unroll
    for (int i = 0; i < 8; i++) {
        int r = (i < 4) ? (ty * 4 + i) : (32 + ty * 4 + i - 4);
        rb[r * 16 + tx] = best[i];
        ri[r * 16 + tx] = bidx[i];
    }
    __syncthreads();
    if (tid < 64) {
        float b = rb[tid * 16]; int ix = ri[tid * 16];
#pragma unroll
        for (int q = 1; q < 16; q++) {
            float s = rb[tid * 16 + q];
            int k2 = ri[tid * 16 + q];
            if (s > b || (s == b && k2 < ix)) { b = s; ix = k2; }
        }
        g_code[r0 + tid] = ix;
    }
}

// ---------------- output ----------------
__global__ __launch_bounds__(256) void k_output(const int* __restrict__ attn_mask,
                                                const float* __restrict__ inv_w,
                                                const float* __restrict__ inv_b,
                                                float* __restrict__ out,
                                                int write_code, float* __restrict__ code_out) {
    __shared__ float es[32][65];
    __shared__ float ws[64][64];
    __shared__ int codes[32];
    __shared__ int msk[32];
    int tid = threadIdx.x;
    int r0 = blockIdx.x * 32;
    if (tid < 32) {
        int i = r0 + tid;
        int c = g_code[i];
        int m = attn_mask[i];
        codes[tid] = c;
        msk[tid] = m;
        if (write_code) code_out[i] = (float)((m == 1) ? c : 0);
    }
    __syncthreads();
    for (int j = tid; j < 32 * 64; j += 256) {
        int r = j >> 6, v = j & 63;
        es[r][v] = (msk[r] == 1) ? g_embed[(size_t)codes[r] * VQ + v] : 0.f;
    }
    int r = tid & 31;
    int ddb = (tid >> 5) * 8;
    for (int d0 = 0; d0 < Dd; d0 += 64) {
        __syncthreads();
        for (int j = tid; j < 64 * 64; j += 256) {
            int dd = j >> 6, v = j & 63;
            ws[dd][v] = inv_w[(size_t)(d0 + dd) * VQ + v];
        }
        __syncthreads();
#pragma unroll
        for (int q = 0; q < 8; q++) {
            int dd = ddb + q;
            float s = inv_b[d0 + dd];
#pragma unroll
            for (int v = 0; v < 64; v += 4) {
                float4 w4 = *(float4*)&ws[dd][v];
                s = fmaf(es[r][v + 0], w4.x, s);
                s = fmaf(es[r][v + 1], w4.y, s);
                s = fmaf(es[r][v + 2], w4.z, s);
                s = fmaf(es[r][v + 3], w4.w, s);
            }
            out[(size_t)(r0 + r) * Dd + d0 + dd] = s;
        }
    }
}

// ---------------- host launcher ----------------
extern "C" void kernel_launch(void* const* d_in, const int* in_sizes, int n_in,
                              void* d_out, int out_size) {
    const float* h_in      = (const float*)d_in[0];
    const int*   attn_mask = (const int*)  d_in[1];
    const float* proj_w    = (const float*)d_in[2];
    const float* proj_b    = (const float*)d_in[3];
    const float* inv_w     = (const float*)d_in[4];
    const float* inv_b     = (const float*)d_in[5];
    const float* mlp_w_in  = (const float*)d_in[6];
    const float* mlp_b_in  = (const float*)d_in[7];
    const float* mlp_w_mid = (const float*)d_in[8];
    const float* mlp_b_mid = (const float*)d_in[9];
    const float* mlp_w_out = (const float*)d_in[10];
    const float* mlp_b_out = (const float*)d_in[11];
    const float* bn_gamma  = (const float*)d_in[12];
    const float* bn_beta   = (const float*)d_in[13];
    float* out = (float*)d_out;

    // independent of codebook path: launch proj first so it overlaps layer0/bn0
    dim3 pg(Tt / 64, Bb);
    k_proj<<<pg, 256>>>(h_in, proj_w, proj_b);

    k_layer0<<<KK * HID / 256, 256>>>(mlp_w_in, mlp_b_in);
    k_bn0<<<HID / 256, 256>>>(mlp_w_in, mlp_b_in, bn_gamma, bn_beta);

    dim3 gg(HID / 128, KK / 128);
    for (int L = 0; L < 4; L++) {
        // GEMM L applies BN_L: stats from layer L-1's fused partials (or BN0 closed form)
        k_gemm<<<gg, 256>>>(L & 1, L, L - 1,
                            mlp_w_mid + (size_t)L * HID * HID, mlp_b_mid + L * HID,
                            bn_gamma + L * HID, bn_beta + L * HID);
    }

    // embed applies BN_4 from layer-3 partials
    k_embed<<<KK / 64, 256>>>(mlp_w_out, mlp_b_out, bn_gamma + 4 * HID, bn_beta + 4 * HID);

    k_argmax<<<BT / 64, 128>>>();

    const long long qelems = (long long)BT * Dd;
    int write_code = (out_size >= qelems + BT) ? 1 : 0;
    k_output<<<BT / 32, 256>>>(attn_mask, inv_w, inv_b, out, write_code, out + qelems);
}

// round 13
// speedup vs baseline: 1.4317x; 1.0579x over previous
#include <cuda_runtime.h>
#include <math.h>

#define Bb 8
#define Tt 2048
#define Dd 768
#define VQ 64
#define L2b 12
#define HID 1024
#define KK 4096
#define BT (Bb*Tt)
#define EPS_N 1e-6f
#define EPS_BN 1e-5f

__device__ float g_z0[KK*HID];
__device__ float g_z1[KK*HID];
__device__ float g_scale[HID];
__device__ float g_shift[HID];
__device__ float g_embed[KK*VQ];
__device__ float g_ck[KK];
__device__ float g_hn[BT*VQ];
__device__ int   g_code[BT];
__device__ float g_psum[4*32*HID];
__device__ float g_psq[4*32*HID];
__device__ unsigned g_ctr[4];

// ---------------- layer 0 ----------------
__global__ void k_layer0(const float* __restrict__ w_in, const float* __restrict__ b_in) {
    int idx = blockIdx.x * blockDim.x + threadIdx.x;
    int k = idx >> 10, h = idx & 1023;
    const float* w = w_in + h * L2b;
    float s = b_in[h];
#pragma unroll
    for (int j = 0; j < L2b; j++)
        if ((k >> (11 - j)) & 1) s += w[j];
    g_z0[idx] = s;
}

// ---------------- BN0 closed form (exact over full enumeration) ----------------
__global__ void k_bn0(const float* __restrict__ w_in, const float* __restrict__ b_in,
                      const float* __restrict__ gamma, const float* __restrict__ beta) {
    int h = blockIdx.x * blockDim.x + threadIdx.x;
    if (h >= HID) return;
    float s = 0.f, q = 0.f;
#pragma unroll
    for (int j = 0; j < L2b; j++) { float w = w_in[h * L2b + j]; s += w; q += w * w; }
    float m = b_in[h] + 0.5f * s;
    float rstd = (float)(1.0 / sqrt(0.25 * (double)q + (double)EPS_BN));
    float sc = gamma[h] * rstd;
    g_scale[h] = sc;
    g_shift[h] = beta[h] - m * sc;
}

#define BN8(BUF) \
    As[BUF][lk+0][lr]=fmaxf(0.f,fmaf(a0.x,s0.x,h0.x)); \
    As[BUF][lk+1][lr]=fmaxf(0.f,fmaf(a0.y,s0.y,h0.y)); \
    As[BUF][lk+2][lr]=fmaxf(0.f,fmaf(a0.z,s0.z,h0.z)); \
    As[BUF][lk+3][lr]=fmaxf(0.f,fmaf(a0.w,s0.w,h0.w)); \
    As[BUF][lk+4][lr]=fmaxf(0.f,fmaf(a1.x,s1.x,h1.x)); \
    As[BUF][lk+5][lr]=fmaxf(0.f,fmaf(a1.y,s1.y,h1.y)); \
    As[BUF][lk+6][lr]=fmaxf(0.f,fmaf(a1.z,s1.z,h1.z)); \
    As[BUF][lk+7][lr]=fmaxf(0.f,fmaf(a1.w,s1.w,h1.w)); \
    Bs[BUF][lk+0][lr]=b0.x; Bs[BUF][lk+1][lr]=b0.y; \
    Bs[BUF][lk+2][lr]=b0.z; Bs[BUF][lk+3][lr]=b0.w; \
    Bs[BUF][lk+4][lr]=b1.x; Bs[BUF][lk+5][lr]=b1.y; \
    Bs[BUF][lk+6][lr]=b1.z; Bs[BUF][lk+7][lr]=b1.w;

// ---------------- mid GEMM: C = relu(bn(A)) @ W^T + bias ----------------
// BN scale/shift read from global (set by bn0 or previous GEMM's tail finalize).
// Tail: last block finalizes BN stats for the NEXT layer into g_scale/g_shift.
__global__ __launch_bounds__(256, 2) void k_gemm(int src, int layer,
                                                 const float* __restrict__ W,
                                                 const float* __restrict__ bias,
                                                 const float* __restrict__ gamma_n,
                                                 const float* __restrict__ beta_n) {
    const float* __restrict__ A = src ? g_z1 : g_z0;
    float* __restrict__ C       = src ? g_z0 : g_z1;
    __shared__ float As[2][16][128];
    __shared__ float Bs[2][16][128];
    __shared__ float s_scale[HID];
    __shared__ float s_shift[HID];
    __shared__ int isLast;
    const int tid = threadIdx.x;
    const int brow = blockIdx.y * 128, bcol = blockIdx.x * 128;
    const int lr = tid >> 1, lk = (tid & 1) * 8;
    const int tx = tid & 15, ty = tid >> 4;

    // cheap copy prologue (8KB from L2)
    for (int h = tid; h < HID; h += 256) {
        s_scale[h] = g_scale[h];
        s_shift[h] = g_shift[h];
    }
    __syncthreads();

    const float* Ap = A + (size_t)(brow + lr) * HID + lk;
    const float* Wp = W + (size_t)(bcol + lr) * HID + lk;
    float4 a0, a1, b0, b1;
    a0 = *(const float4*)Ap;  a1 = *(const float4*)(Ap + 4);
    b0 = *(const float4*)Wp;  b1 = *(const float4*)(Wp + 4);
    {
        float4 s0 = *(const float4*)&s_scale[lk], s1 = *(const float4*)&s_scale[lk + 4];
        float4 h0 = *(const float4*)&s_shift[lk], h1 = *(const float4*)&s_shift[lk + 4];
        BN8(0)
    }
    __syncthreads();
    float acc[8][8] = {};
    for (int t = 0; t < 64; t++) {
        int cur = t & 1, nx = cur ^ 1;
        if (t < 63) {
            int kn = (t + 1) * 16;
            a0 = *(const float4*)(Ap + kn); a1 = *(const float4*)(Ap + kn + 4);
            b0 = *(const float4*)(Wp + kn); b1 = *(const float4*)(Wp + kn + 4);
        }
#pragma unroll
        for (int kk = 0; kk < 16; kk++) {
            float ar[8], br[8];
            *(float4*)&ar[0] = *(const float4*)&As[cur][kk][ty * 4];
            *(float4*)&ar[4] = *(const float4*)&As[cur][kk][64 + ty * 4];
            *(float4*)&br[0] = *(const float4*)&Bs[cur][kk][tx * 4];
            *(float4*)&br[4] = *(const float4*)&Bs[cur][kk][64 + tx * 4];
#pragma unroll
            for (int i = 0; i < 8; i++)
#pragma unroll
                for (int j = 0; j < 8; j++)
                    acc[i][j] = fmaf(ar[i], br[j], acc[i][j]);
        }
        if (t < 63) {
            int kn = (t + 1) * 16 + lk;
            float4 s0 = *(const float4*)&s_scale[kn], s1 = *(const float4*)&s_scale[kn + 4];
            float4 h0 = *(const float4*)&s_shift[kn], h1 = *(const float4*)&s_shift[kn + 4];
            if (nx) { BN8(1) } else { BN8(0) }
        }
        __syncthreads();
    }
    // epilogue: bias + store + column partial stats
    float bj[8];
    *(float4*)&bj[0] = *(const float4*)&bias[bcol + tx * 4];
    *(float4*)&bj[4] = *(const float4*)&bias[bcol + 64 + tx * 4];
    float cs[8] = {}, cq[8] = {};
#pragma unroll
    for (int i = 0; i < 8; i++) {
        int row = brow + ((i < 4) ? (ty * 4 + i) : (64 + ty * 4 + i - 4));
        float v[8];
#pragma unroll
        for (int j = 0; j < 8; j++) {
            v[j] = acc[i][j] + bj[j];
            cs[j] += v[j];
            cq[j] += v[j] * v[j];
        }
        *(float4*)&C[(size_t)row * HID + bcol + tx * 4]      = *(float4*)&v[0];
        *(float4*)&C[(size_t)row * HID + bcol + 64 + tx * 4] = *(float4*)&v[4];
    }
    float* reds = &As[0][0][0];
    float* redq = reds + 2048;
#pragma unroll
    for (int j = 0; j < 8; j++) {
        int c = (j < 4) ? (tx * 4 + j) : (64 + tx * 4 + j - 4);
        reds[ty * 128 + c] = cs[j];
        redq[ty * 128 + c] = cq[j];
    }
    __syncthreads();
    if (tid < 128) {
        float s = 0.f, q = 0.f;
#pragma unroll
        for (int yy = 0; yy < 16; yy++) { s += reds[yy * 128 + tid]; q += redq[yy * 128 + tid]; }
        g_psum[(layer * 32 + blockIdx.y) * HID + bcol + tid] = s;
        g_psq [(layer * 32 + blockIdx.y) * HID + bcol + tid] = q;
    }

    // ---- tail: last block finalizes next layer's BN scale/shift ----
    __threadfence();
    __syncthreads();
    if (tid == 0) {
        unsigned old = atomicAdd(&g_ctr[layer], 1u);
        isLast = (old == 255u);          // grid = 8 x 32 = 256 blocks
    }
    __syncthreads();
    if (isLast) {
        __threadfence();
        const float* ps = g_psum + layer * 32 * HID;
        const float* pq = g_psq + layer * 32 * HID;
        for (int h = tid; h < HID; h += 256) {
            double s = 0.0, q = 0.0;
#pragma unroll 8
            for (int p = 0; p < 32; p++) {
                s += (double)ps[p * HID + h];
                q += (double)pq[p * HID + h];
            }
            double m = s / 4096.0;
            double var = q / 4096.0 - m * m;
            if (var < 0.0) var = 0.0;
            float rstd = (float)(1.0 / sqrt(var + (double)EPS_BN));
            float sc = gamma_n[h] * rstd;
            g_scale[h] = sc;
            g_shift[h] = beta_n[h] - (float)m * sc;
        }
        if (tid == 0) g_ctr[layer] = 0;   // reset for graph replay
    }
}

// ---------------- embed: 64x64 tile GEMM + L2 norm (BN4 scale/shift from global) ----------------
__global__ __launch_bounds__(256) void k_embed(const float* __restrict__ Wout,
                                               const float* __restrict__ bout) {
    __shared__ float As[16][68];
    __shared__ float Ws[16][68];
    __shared__ float red[64][9];
    __shared__ float fac[64];
    __shared__ float s_scale[HID];
    __shared__ float s_shift[HID];
    const int tid = threadIdx.x;
    const int r0 = blockIdx.x * 64;
    const int tx = tid & 7, ty2 = tid >> 3;
    const int lrow = tid >> 2, lkc = (tid & 3) * 4;

    for (int h = tid; h < HID; h += 256) {
        s_scale[h] = g_scale[h];
        s_shift[h] = g_shift[h];
    }
    __syncthreads();

    float acc[2][8] = {};
    for (int k0 = 0; k0 < HID; k0 += 16) {
        {
            float4 a = *(const float4*)&g_z0[(size_t)(r0 + lrow) * HID + k0 + lkc];
            float4 sc = *(const float4*)&s_scale[k0 + lkc];
            float4 sh = *(const float4*)&s_shift[k0 + lkc];
            As[lkc + 0][lrow] = fmaxf(0.f, fmaf(a.x, sc.x, sh.x));
            As[lkc + 1][lrow] = fmaxf(0.f, fmaf(a.y, sc.y, sh.y));
            As[lkc + 2][lrow] = fmaxf(0.f, fmaf(a.z, sc.z, sh.z));
            As[lkc + 3][lrow] = fmaxf(0.f, fmaf(a.w, sc.w, sh.w));
            float4 w = *(const float4*)&Wout[(size_t)lrow * HID + k0 + lkc];
            Ws[lkc + 0][lrow] = w.x; Ws[lkc + 1][lrow] = w.y;
            Ws[lkc + 2][lrow] = w.z; Ws[lkc + 3][lrow] = w.w;
        }
        __syncthreads();
#pragma unroll
        for (int kk = 0; kk < 16; kk++) {
            float2 ap = *(const float2*)&As[kk][ty2 * 2];
            float br[8];
            *(float4*)&br[0] = *(const float4*)&Ws[kk][tx * 8];
            *(float4*)&br[4] = *(const float4*)&Ws[kk][tx * 8 + 4];
#pragma unroll
            for (int j = 0; j < 8; j++) {
                acc[0][j] = fmaf(ap.x, br[j], acc[0][j]);
                acc[1][j] = fmaf(ap.y, br[j], acc[1][j]);
            }
        }
        __syncthreads();
    }
    float bj[8];
    *(float4*)&bj[0] = *(const float4*)&bout[tx * 8];
    *(float4*)&bj[4] = *(const float4*)&bout[tx * 8 + 4];
    float y[2][8];
#pragma unroll
    for (int c = 0; c < 2; c++) {
        float p = 0.f;
#pragma unroll
        for (int j = 0; j < 8; j++) {
            y[c][j] = acc[c][j] + bj[j];
            p = fmaf(y[c][j], y[c][j], p);
        }
        red[ty2 * 2 + c][tx] = p;
    }
    __syncthreads();
    if (tid < 64) {
        float tot = 0.f;
#pragma unroll
        for (int q = 0; q < 8; q++) tot += red[tid][q];
        float f = 1.f / (sqrtf(tot) + EPS_N);
        fac[tid] = f;
        g_ck[r0 + tid] = 0.5f * tot * f * f;
    }
    __syncthreads();
#pragma unroll
    for (int c = 0; c < 2; c++) {
        float f = fac[ty2 * 2 + c];
        float v[8];
#pragma unroll
        for (int j = 0; j < 8; j++) v[j] = y[c][j] * f;
        float* op = &g_embed[(size_t)(r0 + ty2 * 2 + c) * VQ + tx * 8];
        *(float4*)op       = *(float4*)&v[0];
        *(float4*)(op + 4) = *(float4*)&v[4];
    }
}

// ---------------- projection + fused row L2 norm ----------------
__global__ __launch_bounds__(256) void k_proj(const float* __restrict__ h_in,
                                              const float* __restrict__ proj_w,
                                              const float* __restrict__ proj_b) {
    __shared__ float Hs[16][64];
    __shared__ float Ws[16][64];
    __shared__ float red[64][16];
    __shared__ float fac[64];
    int tid = threadIdx.x;
    int b = blockIdx.y;
    int t0 = blockIdx.x * 64;
    int tx = tid & 15, ty = tid >> 4;
    float acc[4][4] = {};
    const float* hb = h_in + (size_t)b * Dd * Tt;
    for (int d0 = 0; d0 < Dd; d0 += 16) {
        {
            int j0 = tid * 4;
            int dd = j0 >> 6, tt = j0 & 63;
            *(float4*)&Hs[dd][tt] = *(const float4*)&hb[(size_t)(d0 + dd) * Tt + t0 + tt];
        }
        {
            int v = tid >> 2, dq = (tid & 3) * 4;
            float4 x = *(const float4*)&proj_w[(size_t)v * Dd + d0 + dq];
            Ws[dq + 0][v] = x.x; Ws[dq + 1][v] = x.y; Ws[dq + 2][v] = x.z; Ws[dq + 3][v] = x.w;
        }
        __syncthreads();
#pragma unroll
        for (int dd = 0; dd < 16; dd++) {
            float ar[4], br[4];
            *(float4*)&ar[0] = *(const float4*)&Hs[dd][ty * 4];
            *(float4*)&br[0] = *(const float4*)&Ws[dd][tx * 4];
#pragma unroll
            for (int i = 0; i < 4; i++)
#pragma unroll
                for (int j = 0; j < 4; j++)
                    acc[i][j] = fmaf(ar[i], br[j], acc[i][j]);
        }
        __syncthreads();
    }
    float bj[4];
    *(float4*)&bj[0] = *(const float4*)&proj_b[tx * 4];
#pragma unroll
    for (int i = 0; i < 4; i++) {
        float p = 0.f;
#pragma unroll
        for (int j = 0; j < 4; j++) {
            float v = acc[i][j] + bj[j];
            acc[i][j] = v;
            p = fmaf(v, v, p);
        }
        red[ty * 4 + i][tx] = p;
    }
    __syncthreads();
    if (tid < 64) {
        float tot = 0.f;
#pragma unroll
        for (int q = 0; q < 16; q++) tot += red[tid][q];
        fac[tid] = 1.f / (sqrtf(tot) + EPS_N);
    }
    __syncthreads();
#pragma unroll
    for (int i = 0; i < 4; i++) {
        float f = fac[ty * 4 + i];
        float v[4];
#pragma unroll
        for (int j = 0; j < 4; j++) v[j] = acc[i][j] * f;
        size_t row = (size_t)b * Tt + t0 + ty * 4 + i;
        *(float4*)&g_hn[row * VQ + tx * 4] = *(float4*)&v[0];
    }
}

// ---------------- argmax: 64 rows x 128 codes/tile, 8x8 microtile ----------------
__global__ __launch_bounds__(128, 4) void k_argmax() {
    __shared__ float hsT[64][64];
    __shared__ float esT[64][128];
    const int tid = threadIdx.x, r0 = blockIdx.x * 64;
    const int tx = tid & 15, ty = tid >> 4;
#pragma unroll
    for (int i = 0; i < 8; i++) {
        int f = tid + i * 128;
        int r = f >> 4, vq = (f & 15) * 4;
        float4 x = *(const float4*)&g_hn[(size_t)(r0 + r) * VQ + vq];
        hsT[vq + 0][r] = x.x; hsT[vq + 1][r] = x.y;
        hsT[vq + 2][r] = x.z; hsT[vq + 3][r] = x.w;
    }
    float best[8]; int bidx[8];
#pragma unroll
    for (int i = 0; i < 8; i++) { best[i] = -3.4e38f; bidx[i] = 0; }

    for (int kt = 0; kt < 32; kt++) {
        int kb = kt * 128;
        __syncthreads();
#pragma unroll
        for (int i = 0; i < 16; i++) {
            int f = tid + i * 128;
            int code = f >> 4, vq = (f & 15) * 4;
            float4 x = *(const float4*)&g_embed[(size_t)(kb + code) * VQ + vq];
            esT[vq + 0][code] = x.x; esT[vq + 1][code] = x.y;
            esT[vq + 2][code] = x.z; esT[vq + 3][code] = x.w;
        }
        __syncthreads();
        float acc[8][8] = {};
#pragma unroll 4
        for (int v = 0; v < 64; v++) {
            float ar[8], br[8];
            *(float4*)&ar[0] = *(const float4*)&hsT[v][ty * 4];
            *(float4*)&ar[4] = *(const float4*)&hsT[v][32 + ty * 4];
            *(float4*)&br[0] = *(const float4*)&esT[v][tx * 4];
            *(float4*)&br[4] = *(const float4*)&esT[v][64 + tx * 4];
#pragma unroll
            for (int i = 0; i < 8; i++)
#pragma unroll
                for (int j = 0; j < 8; j++)
                    acc[i][j] = fmaf(ar[i], br[j], acc[i][j]);
        }
#pragma unroll
        for (int j = 0; j < 8; j++) {
            int kg = kb + ((j < 4) ? (tx * 4 + j) : (64 + tx * 4 + j - 4));
            float ck = g_ck[kg];
#pragma unroll
            for (int i = 0; i < 8; i++) {
                float s = acc[i][j] - ck;
                if (s > best[i]) { best[i] = s; bidx[i] = kg; }
            }
        }
    }
    __syncthreads();
    float* rb = &esT[0][0];
    int* ri = (int*)(rb + 1024);
#pragma unroll
    for (int i = 0; i < 8; i++) {
        int r = (i < 4) ? (ty * 4 + i) : (32 + ty * 4 + i - 4);
        rb[r * 16 + tx] = best[i];
        ri[r * 16 + tx] = bidx[i];
    }
    __syncthreads();
    if (tid < 64) {
        float b = rb[tid * 16]; int ix = ri[tid * 16];
#pragma unroll
        for (int q = 1; q < 16; q++) {
            float s = rb[tid * 16 + q];
            int k2 = ri[tid * 16 + q];
            if (s > b || (s == b && k2 < ix)) { b = s; ix = k2; }
        }
        g_code[r0 + tid] = ix;
    }
}

// ---------------- output ----------------
__global__ __launch_bounds__(256) void k_output(const int* __restrict__ attn_mask,
                                                const float* __restrict__ inv_w,
                                                const float* __restrict__ inv_b,
                                                float* __restrict__ out,
                                                int write_code, float* __restrict__ code_out) {
    __shared__ float es[32][65];
    __shared__ float ws[64][64];
    __shared__ int codes[32];
    __shared__ int msk[32];
    int tid = threadIdx.x;
    int r0 = blockIdx.x * 32;
    if (tid < 32) {
        int i = r0 + tid;
        int c = g_code[i];
        int m = attn_mask[i];
        codes[tid] = c;
        msk[tid] = m;
        if (write_code) code_out[i] = (float)((m == 1) ? c : 0);
    }
    __syncthreads();
    for (int j = tid; j < 32 * 64; j += 256) {
        int r = j >> 6, v = j & 63;
        es[r][v] = (msk[r] == 1) ? g_embed[(size_t)codes[r] * VQ + v] : 0.f;
    }
    int r = tid & 31;
    int ddb = (tid >> 5) * 8;
    for (int d0 = 0; d0 < Dd; d0 += 64) {
        __syncthreads();
        for (int j = tid; j < 64 * 64; j += 256) {
            int dd = j >> 6, v = j & 63;
            ws[dd][v] = inv_w[(size_t)(d0 + dd) * VQ + v];
        }
        __syncthreads();
#pragma unroll
        for (int q = 0; q < 8; q++) {
            int dd = ddb + q;
            float s = inv_b[d0 + dd];
#pragma unroll
            for (int v = 0; v < 64; v += 4) {
                float4 w4 = *(float4*)&ws[dd][v];
                s = fmaf(es[r][v + 0], w4.x, s);
                s = fmaf(es[r][v + 1], w4.y, s);
                s = fmaf(es[r][v + 2], w4.z, s);
                s = fmaf(es[r][v + 3], w4.w, s);
            }
            out[(size_t)(r0 + r) * Dd + d0 + dd] = s;
        }
    }
}

// ---------------- host launcher ----------------
extern "C" void kernel_launch(void* const* d_in, const int* in_sizes, int n_in,
                              void* d_out, int out_size) {
    const float* h_in      = (const float*)d_in[0];
    const int*   attn_mask = (const int*)  d_in[1];
    const float* proj_w    = (const float*)d_in[2];
    const float* proj_b    = (const float*)d_in[3];
    const float* inv_w     = (const float*)d_in[4];
    const float* inv_b     = (const float*)d_in[5];
    const float* mlp_w_in  = (const float*)d_in[6];
    const float* mlp_b_in  = (const float*)d_in[7];
    const float* mlp_w_mid = (const float*)d_in[8];
    const float* mlp_b_mid = (const float*)d_in[9];
    const float* mlp_w_out = (const float*)d_in[10];
    const float* mlp_b_out = (const float*)d_in[11];
    const float* bn_gamma  = (const float*)d_in[12];
    const float* bn_beta   = (const float*)d_in[13];
    float* out = (float*)d_out;

    // independent of codebook path: launch proj first so it overlaps layer0/bn0
    dim3 pg(Tt / 64, Bb);
    k_proj<<<pg, 256>>>(h_in, proj_w, proj_b);

    k_layer0<<<KK * HID / 256, 256>>>(mlp_w_in, mlp_b_in);
    k_bn0<<<HID / 256, 256>>>(mlp_w_in, mlp_b_in, bn_gamma, bn_beta);

    dim3 gg(HID / 128, KK / 128);
    for (int L = 0; L < 4; L++) {
        // GEMM L applies BN_L (global g_scale/g_shift), tail-finalizes BN_{L+1}
        k_gemm<<<gg, 256>>>(L & 1, L,
                            mlp_w_mid + (size_t)L * HID * HID, mlp_b_mid + L * HID,
                            bn_gamma + (L + 1) * HID, bn_beta + (L + 1) * HID);
    }

    // embed applies BN_4 (finalized by layer-3 GEMM tail)
    k_embed<<<KK / 64, 256>>>(mlp_w_out, mlp_b_out);

    k_argmax<<<BT / 64, 128>>>();

    const long long qelems = (long long)BT * Dd;
    int write_code = (out_size >= qelems + BT) ? 1 : 0;
    k_output<<<BT / 32, 256>>>(attn_mask, inv_w, inv_b, out, write_code, out + qelems);
}